// round 1
// baseline (speedup 1.0000x reference)
#include <cuda_runtime.h>
#include <math.h>

// Problem constants
#define BB 8
#define NN 2048
#define PTS (BB*NN)      // 16384
#define DD 64
#define KK 8
#define LV 3
#define H1 256
#define H2 128

// Scratch (device globals; no allocation allowed)
__device__ float g_A  [PTS*DD];
__device__ float g_Bf [PTS*DD];
__device__ float g_fw [PTS*LV];
__device__ int   g_idx[PTS*KK];
__device__ float g_agg[PTS*DD];

__device__ __forceinline__ float leaky(float v){ return v > 0.f ? v : 0.2f*v; }

__device__ __forceinline__ unsigned long long ffma2(unsigned long long a, unsigned long long b, unsigned long long c){
    unsigned long long d;
    asm("fma.rn.f32x2 %0, %1, %2, %3;" : "=l"(d) : "l"(a), "l"(b), "l"(c));
    return d;
}
__device__ __forceinline__ unsigned long long pack2(float w){
    unsigned long long r;
    asm("mov.b64 %0, {%1, %1};" : "=l"(r) : "f"(w));
    return r;
}

// ---------------------------------------------------------------------------
// K1: per-point prep: feat = leaky((x@W1+b1)*g1+be1);
//     A = feat@W2[:64] + b2 ; Bf = feat@W2[64:] ;
//     fw = sigmoid(relu(x@Ws1+bs1)@Ws2+bs2)
// grid 256 blocks x 256 threads, 64 points/block
// ---------------------------------------------------------------------------
__global__ void k_prep(const float* __restrict__ x,
                       const float* __restrict__ W1, const float* __restrict__ b1,
                       const float* __restrict__ g1, const float* __restrict__ be1,
                       const float* __restrict__ W2, const float* __restrict__ b2,
                       const float* __restrict__ Ws1, const float* __restrict__ bs1,
                       const float* __restrict__ Ws2, const float* __restrict__ bs2)
{
    extern __shared__ float sm[];
    float* W2s   = sm;               // 128*64 = 8192
    float* featS = W2s + 8192;       // 64*65  = 4160 (padded)
    float* ssS   = featS + 4160;     // 64*64  = 4096
    float* W1s   = ssS + 4096;       // 192
    float* Ws1s  = W1s + 192;        // 192
    float* Ws2s  = Ws1s + 192;       // 192
    float* b1v   = Ws2s + 192;       // 64
    float* g1v   = b1v + 64;
    float* be1v  = g1v + 64;
    float* b2v   = be1v + 64;
    float* bs1v  = b2v + 64;
    float* bs2v  = bs1v + 64;        // 4
    float* xs    = bs2v + 4;         // 192

    const int tid = threadIdx.x;
    const int p0  = blockIdx.x * 64;

    for (int i = tid; i < 8192; i += 256) W2s[i] = W2[i];
    for (int i = tid; i < 192; i += 256) { W1s[i] = W1[i]; Ws1s[i] = Ws1[i]; Ws2s[i] = Ws2[i]; xs[i] = x[p0*3 + i]; }
    if (tid < 64) { b1v[tid]=b1[tid]; g1v[tid]=g1[tid]; be1v[tid]=be1[tid]; b2v[tid]=b2[tid]; bs1v[tid]=bs1[tid]; }
    if (tid < 3)  bs2v[tid] = bs2[tid];
    __syncthreads();

    for (int i = tid; i < 4096; i += 256) {
        int pt = i >> 6, d = i & 63;
        float x0 = xs[pt*3], x1 = xs[pt*3+1], x2 = xs[pt*3+2];
        float f = fmaf(x2, W1s[128+d], fmaf(x1, W1s[64+d], fmaf(x0, W1s[d], b1v[d])));
        f = fmaf(f, g1v[d], be1v[d]);
        featS[pt*65 + d] = leaky(f);
        float s = fmaf(x2, Ws1s[128+d], fmaf(x1, Ws1s[64+d], fmaf(x0, Ws1s[d], bs1v[d])));
        ssS[pt*64 + d] = s > 0.f ? s : 0.f;
    }
    __syncthreads();

    if (tid < 192) {
        int pt = tid / 3, l = tid - pt*3;
        float s = bs2v[l];
        #pragma unroll 8
        for (int d = 0; d < 64; d++) s = fmaf(ssS[pt*64 + d], Ws2s[d*3 + l], s);
        g_fw[(p0+pt)*3 + l] = 1.f / (1.f + expf(-s));
    }

    // A / Bf : thread = (pt, group of 16 output dims)
    int pt  = tid & 63;
    int grp = tid >> 6;
    float accA[16], accB[16];
    #pragma unroll
    for (int u = 0; u < 16; u++) { accA[u] = b2v[grp*16 + u]; accB[u] = 0.f; }
    for (int d = 0; d < 64; d++) {
        float fv = featS[pt*65 + d];
        const float4* wa = (const float4*)(W2s + d*64       + grp*16);
        const float4* wb = (const float4*)(W2s + (64+d)*64  + grp*16);
        #pragma unroll
        for (int u = 0; u < 4; u++) {
            float4 a = wa[u], b = wb[u];
            accA[4*u+0] = fmaf(fv, a.x, accA[4*u+0]);
            accA[4*u+1] = fmaf(fv, a.y, accA[4*u+1]);
            accA[4*u+2] = fmaf(fv, a.z, accA[4*u+2]);
            accA[4*u+3] = fmaf(fv, a.w, accA[4*u+3]);
            accB[4*u+0] = fmaf(fv, b.x, accB[4*u+0]);
            accB[4*u+1] = fmaf(fv, b.y, accB[4*u+1]);
            accB[4*u+2] = fmaf(fv, b.z, accB[4*u+2]);
            accB[4*u+3] = fmaf(fv, b.w, accB[4*u+3]);
        }
    }
    float4* pA = (float4*)(g_A  + (p0+pt)*64 + grp*16);
    float4* pB = (float4*)(g_Bf + (p0+pt)*64 + grp*16);
    #pragma unroll
    for (int u = 0; u < 4; u++) {
        pA[u] = make_float4(accA[4*u], accA[4*u+1], accA[4*u+2], accA[4*u+3]);
        pB[u] = make_float4(accB[4*u], accB[4*u+1], accB[4*u+2], accB[4*u+3]);
    }
}

// ---------------------------------------------------------------------------
// K2: KNN. grid (32, 8): 64 points/block, 4 j-splits x 64 pts = 256 threads.
// d2 = (x2_i + x2_j) - 2*dot ; stable top-8 by (d2, idx) lexicographic.
// ---------------------------------------------------------------------------
__global__ void k_knn(const float* __restrict__ x)
{
    extern __shared__ float sm[];
    float4* xsh = (float4*)sm;            // 2048 * 4 floats = 8192 floats
    float*  md  = sm + 8192;              // 64*33
    int*    mi  = (int*)(md + 64*33);     // 64*33

    const int tid = threadIdx.x;
    const int b   = blockIdx.y;
    const int pl0 = blockIdx.x * 64;

    for (int j = tid; j < NN; j += 256) {
        const float* xp = x + (b*NN + j)*3;
        float x0 = xp[0], x1 = xp[1], x2 = xp[2];
        float n  = fmaf(x2, x2, fmaf(x1, x1, x0*x0));
        xsh[j] = make_float4(x0, x1, x2, n);
    }
    __syncthreads();

    const int pt = tid & 63, split = tid >> 6;
    float4 xi = xsh[pl0 + pt];
    float bd[8]; int bi[8];
    #pragma unroll
    for (int s = 0; s < 8; s++) { bd[s] = 3.4e38f; bi[s] = 0x7fffffff; }

    const int j0 = split * 512;
    #pragma unroll 4
    for (int j = j0; j < j0 + 512; j++) {
        float4 xj = xsh[j];
        float dot = fmaf(xi.z, xj.z, fmaf(xi.y, xj.y, xi.x*xj.x));
        float d2  = fmaf(-2.f, dot, xi.w + xj.w);
        if (d2 < bd[7]) {   // ties never insert (scanning j ascending -> stable)
            int pos = 7;
            #pragma unroll
            for (int s = 6; s >= 0; s--) if (d2 < bd[s]) pos = s;
            #pragma unroll
            for (int s = 7; s >= 1; s--) if (s > pos) { bd[s] = bd[s-1]; bi[s] = bi[s-1]; }
            bd[pos] = d2; bi[pos] = j;
        }
    }
    #pragma unroll
    for (int s = 0; s < 8; s++) { md[pt*33 + split*8 + s] = bd[s]; mi[pt*33 + split*8 + s] = bi[s]; }
    __syncthreads();

    if (tid < 64) {
        float fd[8]; int fi[8];
        #pragma unroll
        for (int s = 0; s < 8; s++) { fd[s] = 3.4e38f; fi[s] = 0x7fffffff; }
        for (int c = 0; c < 32; c++) {
            float cd = md[tid*33 + c]; int ci = mi[tid*33 + c];
            bool ins = (cd < fd[7]) || (cd == fd[7] && ci < fi[7]);
            if (ins) {
                int pos = 7;
                #pragma unroll
                for (int s = 6; s >= 0; s--) if (cd < fd[s] || (cd == fd[s] && ci < fi[s])) pos = s;
                #pragma unroll
                for (int s = 7; s >= 1; s--) if (s > pos) { fd[s] = fd[s-1]; fi[s] = fi[s-1]; }
                fd[pos] = cd; fi[pos] = ci;
            }
        }
        int gp = b*NN + pl0 + tid;
        #pragma unroll
        for (int s = 0; s < 8; s++) g_idx[gp*8 + s] = fi[s];
    }
}

// ---------------------------------------------------------------------------
// K3: gather + edge-conv epilogue + max over k.
// agg[p][t] = max_k leaky((A[p][t] + Bf[idx[p][k]][t]) * g2[t] + be2[t])
// grid 4096 x 256 : 4 points/block x 64 dims
// ---------------------------------------------------------------------------
__global__ void k_edge(const float* __restrict__ g2v, const float* __restrict__ be2v)
{
    __shared__ int idxS[32];
    const int tid = threadIdx.x;
    const int ptl = tid >> 6, t = tid & 63;
    const int p0  = blockIdx.x * 4;
    if (tid < 32) idxS[tid] = g_idx[p0*8 + tid];
    __syncthreads();

    const int p = p0 + ptl;
    const int bbase = (p >> 11) << 11;   // b * 2048
    float a  = g_A[p*64 + t];
    float g  = g2v[t], be = be2v[t];
    float m  = -3.4e38f;
    #pragma unroll
    for (int k = 0; k < 8; k++) {
        int j = idxS[ptl*8 + k];
        float v = g_Bf[(bbase + j)*64 + t];
        float c = fmaf(a + v, g, be);
        c = leaky(c);
        m = fmaxf(m, c);
    }
    g_agg[p*64 + t] = m;
}

// ---------------------------------------------------------------------------
// K4: fusion MLP 192->256->128->3 + residual. FFMA2-packed (2 points/op).
// grid 256 x 256 : 64 points/block, 8 warps, 8 points/warp.
// ---------------------------------------------------------------------------
__global__ void k_fuse(const float* __restrict__ x,
                       const float* __restrict__ Wf1, const float* __restrict__ bf1,
                       const float* __restrict__ gf1, const float* __restrict__ bef1,
                       const float* __restrict__ Wf2, const float* __restrict__ bf2,
                       const float* __restrict__ gf2, const float* __restrict__ bef2,
                       const float* __restrict__ Wf3, const float* __restrict__ bf3,
                       float* __restrict__ out)
{
    extern __shared__ float sm[];
    float* aggS   = sm;                  // 64*65  = 4160
    float* fwS    = aggS + 4160;         // 192
    float* b1S    = fwS + 192;           // 256
    float* g1S    = b1S + 256;           // 256
    float* e1S    = g1S + 256;           // 256
    float* b2S    = e1S + 256;           // 128
    float* g2S    = b2S + 128;           // 128
    float* e2S    = g2S + 128;           // 128
    float* multiT = e2S + 128;           // 192*64 = 12288  [k][pt]
    float* h1T    = multiT + 12288;      // 256*66 = 16896  [o][pt] padded
    float* h2T    = h1T + 16896;         // 128*66 = 8448

    const int tid = threadIdx.x;
    const int p0  = blockIdx.x * 64;

    for (int i = tid; i < 4096; i += 256) { int pt = i >> 6, d = i & 63; aggS[pt*65 + d] = g_agg[(p0+pt)*64 + d]; }
    if (tid < 192) fwS[tid] = g_fw[p0*3 + tid];
    if (tid < 256) { b1S[tid] = bf1[tid]; g1S[tid] = gf1[tid]; e1S[tid] = bef1[tid]; }
    if (tid < 128) { b2S[tid] = bf2[tid]; g2S[tid] = gf2[tid]; e2S[tid] = bef2[tid]; }
    __syncthreads();

    // multi[k = l*64+d][pt] = agg[pt][d] * fw[pt][l]
    for (int i = tid; i < 12288; i += 256) {
        int pt = i & 63, k = i >> 6;
        multiT[k*64 + pt] = aggS[pt*65 + (k & 63)] * fwS[pt*3 + (k >> 6)];
    }
    __syncthreads();

    const int w = tid >> 5, lane = tid & 31;
    const int base = 8 * w;   // this warp's 8 points

    // ---- layer 1: 192 -> 256 ----
    unsigned long long acc[8][4];
    #pragma unroll
    for (int r = 0; r < 8; r++)
        #pragma unroll
        for (int q = 0; q < 4; q++) acc[r][q] = 0ull;

    #pragma unroll 2
    for (int k = 0; k < 192; k++) {
        const unsigned long long* mp = (const unsigned long long*)(multiT + k*64 + base);
        unsigned long long in0 = mp[0], in1 = mp[1], in2 = mp[2], in3 = mp[3];
        #pragma unroll
        for (int r = 0; r < 8; r++) {
            unsigned long long wp = pack2(Wf1[k*256 + lane + 32*r]);
            acc[r][0] = ffma2(in0, wp, acc[r][0]);
            acc[r][1] = ffma2(in1, wp, acc[r][1]);
            acc[r][2] = ffma2(in2, wp, acc[r][2]);
            acc[r][3] = ffma2(in3, wp, acc[r][3]);
        }
    }
    #pragma unroll
    for (int r = 0; r < 8; r++) {
        int o = lane + 32*r;
        float bb = b1S[o], gg = g1S[o], ee = e1S[o];
        #pragma unroll
        for (int q = 0; q < 4; q++) {
            float2 v = *(float2*)&acc[r][q];
            float v0 = leaky(fmaf(v.x + bb, gg, ee));
            float v1 = leaky(fmaf(v.y + bb, gg, ee));
            *(float2*)(h1T + o*66 + base + 2*q) = make_float2(v0, v1);
        }
    }
    __syncwarp();

    // ---- layer 2: 256 -> 128 ----
    unsigned long long a2[4][4];
    #pragma unroll
    for (int r = 0; r < 4; r++)
        #pragma unroll
        for (int q = 0; q < 4; q++) a2[r][q] = 0ull;

    #pragma unroll 2
    for (int k = 0; k < 256; k++) {
        const unsigned long long* hp = (const unsigned long long*)(h1T + k*66 + base);
        unsigned long long in0 = hp[0], in1 = hp[1], in2 = hp[2], in3 = hp[3];
        #pragma unroll
        for (int r = 0; r < 4; r++) {
            unsigned long long wp = pack2(Wf2[k*128 + lane + 32*r]);
            a2[r][0] = ffma2(in0, wp, a2[r][0]);
            a2[r][1] = ffma2(in1, wp, a2[r][1]);
            a2[r][2] = ffma2(in2, wp, a2[r][2]);
            a2[r][3] = ffma2(in3, wp, a2[r][3]);
        }
    }
    #pragma unroll
    for (int r = 0; r < 4; r++) {
        int o = lane + 32*r;
        float bb = b2S[o], gg = g2S[o], ee = e2S[o];
        #pragma unroll
        for (int q = 0; q < 4; q++) {
            float2 v = *(float2*)&a2[r][q];
            float v0 = leaky(fmaf(v.x + bb, gg, ee));
            float v1 = leaky(fmaf(v.y + bb, gg, ee));
            *(float2*)(h2T + o*66 + base + 2*q) = make_float2(v0, v1);
        }
    }
    __syncwarp();

    // ---- layer 3: 128 -> 3 + residual ----
    if (lane < 24) {
        int pt = lane / 3, c = lane - pt*3;
        float s0 = 0.f, s1 = 0.f;
        #pragma unroll 4
        for (int k = 0; k < 128; k += 2) {
            s0 = fmaf(h2T[k*66     + base + pt], Wf3[k*3 + c],     s0);
            s1 = fmaf(h2T[(k+1)*66 + base + pt], Wf3[(k+1)*3 + c], s1);
        }
        int gp = p0 + base + pt;
        out[gp*3 + c] = fmaf(0.1f, (s0 + s1) + bf3[c], x[gp*3 + c]);
    }
}

// ---------------------------------------------------------------------------
extern "C" void kernel_launch(void* const* d_in, const int* in_sizes, int n_in,
                              void* d_out, int out_size)
{
    const float* x    = (const float*)d_in[0];
    const float* W1   = (const float*)d_in[1];
    const float* b1   = (const float*)d_in[2];
    const float* g1   = (const float*)d_in[3];
    const float* be1  = (const float*)d_in[4];
    const float* W2   = (const float*)d_in[5];
    const float* b2   = (const float*)d_in[6];
    const float* g2   = (const float*)d_in[7];
    const float* be2  = (const float*)d_in[8];
    const float* Ws1  = (const float*)d_in[9];
    const float* bs1  = (const float*)d_in[10];
    const float* Ws2  = (const float*)d_in[11];
    const float* bs2  = (const float*)d_in[12];
    const float* Wf1  = (const float*)d_in[13];
    const float* bf1  = (const float*)d_in[14];
    const float* gf1  = (const float*)d_in[15];
    const float* bef1 = (const float*)d_in[16];
    const float* Wf2  = (const float*)d_in[17];
    const float* bf2  = (const float*)d_in[18];
    const float* gf2  = (const float*)d_in[19];
    const float* bef2 = (const float*)d_in[20];
    const float* Wf3  = (const float*)d_in[21];
    const float* bf3  = (const float*)d_in[22];
    float* out = (float*)d_out;

    const int SM1 = 17540 * 4;   // k_prep shared floats
    const int SM2 = 49664;       // k_knn shared bytes
    const int SM4 = 43136 * 4;   // k_fuse shared bytes

    cudaFuncSetAttribute(k_prep, cudaFuncAttributeMaxDynamicSharedMemorySize, SM1);
    cudaFuncSetAttribute(k_knn,  cudaFuncAttributeMaxDynamicSharedMemorySize, SM2);
    cudaFuncSetAttribute(k_fuse, cudaFuncAttributeMaxDynamicSharedMemorySize, SM4);

    k_prep<<<256, 256, SM1>>>(x, W1, b1, g1, be1, W2, b2, Ws1, bs1, Ws2, bs2);
    k_knn<<<dim3(32, 8), 256, SM2>>>(x);
    k_edge<<<4096, 256>>>(g2, be2);
    k_fuse<<<256, 256, SM4>>>(x, Wf1, bf1, gf1, bef1, Wf2, bf2, gf2, bef2, Wf3, bf3, out);
}

// round 3
// speedup vs baseline: 1.2519x; 1.2519x over previous
#include <cuda_runtime.h>
#include <math.h>

// Problem constants
#define BB 8
#define NN 2048
#define PTS (BB*NN)      // 16384
#define DD 64
#define KK 8
#define LV 3
#define H1 256
#define H2 128
#define PTB 32           // points per k_fuse block

// Scratch (device globals; no allocation allowed)
__device__ float g_A  [PTS*DD];
__device__ float g_Bf [PTS*DD];
__device__ float g_fw [PTS*LV];
__device__ int   g_idx[PTS*KK];

__device__ __forceinline__ float leaky(float v){ return v > 0.f ? v : 0.2f*v; }

__device__ __forceinline__ unsigned long long ffma2(unsigned long long a, unsigned long long b, unsigned long long c){
    unsigned long long d;
    asm("fma.rn.f32x2 %0, %1, %2, %3;" : "=l"(d) : "l"(a), "l"(b), "l"(c));
    return d;
}
__device__ __forceinline__ unsigned long long pack2(float w){
    unsigned long long r;
    asm("mov.b64 %0, {%1, %1};" : "=l"(r) : "f"(w));
    return r;
}

// ---------------------------------------------------------------------------
// K1: per-point prep: feat = leaky((x@W1+b1)*g1+be1);
//     A = feat@W2[:64] + b2 ; Bf = feat@W2[64:] ;
//     fw = sigmoid(relu(x@Ws1+bs1)@Ws2+bs2)
// ---------------------------------------------------------------------------
__global__ void k_prep(const float* __restrict__ x,
                       const float* __restrict__ W1, const float* __restrict__ b1,
                       const float* __restrict__ g1, const float* __restrict__ be1,
                       const float* __restrict__ W2, const float* __restrict__ b2,
                       const float* __restrict__ Ws1, const float* __restrict__ bs1,
                       const float* __restrict__ Ws2, const float* __restrict__ bs2)
{
    extern __shared__ float sm[];
    float* W2s   = sm;               // 128*64 = 8192
    float* featS = W2s + 8192;       // 64*65  = 4160 (padded)
    float* ssS   = featS + 4160;     // 64*64  = 4096
    float* W1s   = ssS + 4096;       // 192
    float* Ws1s  = W1s + 192;        // 192
    float* Ws2s  = Ws1s + 192;       // 192
    float* b1v   = Ws2s + 192;       // 64
    float* g1v   = b1v + 64;
    float* be1v  = g1v + 64;
    float* b2v   = be1v + 64;
    float* bs1v  = b2v + 64;
    float* bs2v  = bs1v + 64;        // 4
    float* xs    = bs2v + 4;         // 192

    const int tid = threadIdx.x;
    const int p0  = blockIdx.x * 64;

    for (int i = tid; i < 8192; i += 256) W2s[i] = W2[i];
    for (int i = tid; i < 192; i += 256) { W1s[i] = W1[i]; Ws1s[i] = Ws1[i]; Ws2s[i] = Ws2[i]; xs[i] = x[p0*3 + i]; }
    if (tid < 64) { b1v[tid]=b1[tid]; g1v[tid]=g1[tid]; be1v[tid]=be1[tid]; b2v[tid]=b2[tid]; bs1v[tid]=bs1[tid]; }
    if (tid < 3)  bs2v[tid] = bs2[tid];
    __syncthreads();

    for (int i = tid; i < 4096; i += 256) {
        int pt = i >> 6, d = i & 63;
        float x0 = xs[pt*3], x1 = xs[pt*3+1], x2 = xs[pt*3+2];
        float f = fmaf(x2, W1s[128+d], fmaf(x1, W1s[64+d], fmaf(x0, W1s[d], b1v[d])));
        f = fmaf(f, g1v[d], be1v[d]);
        featS[pt*65 + d] = leaky(f);
        float s = fmaf(x2, Ws1s[128+d], fmaf(x1, Ws1s[64+d], fmaf(x0, Ws1s[d], bs1v[d])));
        ssS[pt*64 + d] = s > 0.f ? s : 0.f;
    }
    __syncthreads();

    if (tid < 192) {
        int pt = tid / 3, l = tid - pt*3;
        float s = bs2v[l];
        #pragma unroll 8
        for (int d = 0; d < 64; d++) s = fmaf(ssS[pt*64 + d], Ws2s[d*3 + l], s);
        g_fw[(p0+pt)*3 + l] = 1.f / (1.f + expf(-s));
    }

    // A / Bf : thread = (pt, group of 16 output dims)
    int pt  = tid & 63;
    int grp = tid >> 6;
    float accA[16], accB[16];
    #pragma unroll
    for (int u = 0; u < 16; u++) { accA[u] = b2v[grp*16 + u]; accB[u] = 0.f; }
    for (int d = 0; d < 64; d++) {
        float fv = featS[pt*65 + d];
        const float4* wa = (const float4*)(W2s + d*64       + grp*16);
        const float4* wb = (const float4*)(W2s + (64+d)*64  + grp*16);
        #pragma unroll
        for (int u = 0; u < 4; u++) {
            float4 a = wa[u], b = wb[u];
            accA[4*u+0] = fmaf(fv, a.x, accA[4*u+0]);
            accA[4*u+1] = fmaf(fv, a.y, accA[4*u+1]);
            accA[4*u+2] = fmaf(fv, a.z, accA[4*u+2]);
            accA[4*u+3] = fmaf(fv, a.w, accA[4*u+3]);
            accB[4*u+0] = fmaf(fv, b.x, accB[4*u+0]);
            accB[4*u+1] = fmaf(fv, b.y, accB[4*u+1]);
            accB[4*u+2] = fmaf(fv, b.z, accB[4*u+2]);
            accB[4*u+3] = fmaf(fv, b.w, accB[4*u+3]);
        }
    }
    float4* pA = (float4*)(g_A  + (p0+pt)*64 + grp*16);
    float4* pB = (float4*)(g_Bf + (p0+pt)*64 + grp*16);
    #pragma unroll
    for (int u = 0; u < 4; u++) {
        pA[u] = make_float4(accA[4*u], accA[4*u+1], accA[4*u+2], accA[4*u+3]);
        pB[u] = make_float4(accB[4*u], accB[4*u+1], accB[4*u+2], accB[4*u+3]);
    }
}

// ---------------------------------------------------------------------------
// K2: KNN. grid (32, 8): 64 points/block, 4 j-splits x 64 pts = 256 threads.
// ---------------------------------------------------------------------------
__global__ void k_knn(const float* __restrict__ x)
{
    extern __shared__ float sm[];
    float4* xsh = (float4*)sm;            // 2048 * 4 floats
    float*  md  = sm + 8192;              // 64*33
    int*    mi  = (int*)(md + 64*33);     // 64*33

    const int tid = threadIdx.x;
    const int b   = blockIdx.y;
    const int pl0 = blockIdx.x * 64;

    for (int j = tid; j < NN; j += 256) {
        const float* xp = x + (b*NN + j)*3;
        float x0 = xp[0], x1 = xp[1], x2 = xp[2];
        float n  = fmaf(x2, x2, fmaf(x1, x1, x0*x0));
        xsh[j] = make_float4(x0, x1, x2, n);
    }
    __syncthreads();

    const int pt = tid & 63, split = tid >> 6;
    float4 xi = xsh[pl0 + pt];
    float bd[8]; int bi[8];
    #pragma unroll
    for (int s = 0; s < 8; s++) { bd[s] = 3.4e38f; bi[s] = 0x7fffffff; }

    const int j0 = split * 512;
    #pragma unroll 4
    for (int j = j0; j < j0 + 512; j++) {
        float4 xj = xsh[j];
        float dot = fmaf(xi.z, xj.z, fmaf(xi.y, xj.y, xi.x*xj.x));
        float d2  = fmaf(-2.f, dot, xi.w + xj.w);
        if (d2 < bd[7]) {
            int pos = 7;
            #pragma unroll
            for (int s = 6; s >= 0; s--) if (d2 < bd[s]) pos = s;
            #pragma unroll
            for (int s = 7; s >= 1; s--) if (s > pos) { bd[s] = bd[s-1]; bi[s] = bi[s-1]; }
            bd[pos] = d2; bi[pos] = j;
        }
    }
    #pragma unroll
    for (int s = 0; s < 8; s++) { md[pt*33 + split*8 + s] = bd[s]; mi[pt*33 + split*8 + s] = bi[s]; }
    __syncthreads();

    if (tid < 64) {
        float fd[8]; int fi[8];
        #pragma unroll
        for (int s = 0; s < 8; s++) { fd[s] = 3.4e38f; fi[s] = 0x7fffffff; }
        for (int c = 0; c < 32; c++) {
            float cd = md[tid*33 + c]; int ci = mi[tid*33 + c];
            bool ins = (cd < fd[7]) || (cd == fd[7] && ci < fi[7]);
            if (ins) {
                int pos = 7;
                #pragma unroll
                for (int s = 6; s >= 0; s--) if (cd < fd[s] || (cd == fd[s] && ci < fi[s])) pos = s;
                #pragma unroll
                for (int s = 7; s >= 1; s--) if (s > pos) { fd[s] = fd[s-1]; fi[s] = fi[s-1]; }
                fd[pos] = cd; fi[pos] = ci;
            }
        }
        int gp = b*NN + pl0 + tid;
        #pragma unroll
        for (int s = 0; s < 8; s++) g_idx[gp*8 + s] = fi[s];
    }
}

// ---------------------------------------------------------------------------
// K3 (fused): gather+edge-max+fw -> multiT (smem), then fusion MLP.
// 32 points/block, 256 threads, ~100KB smem -> 2 blocks/SM.
// Weights staged cooperatively into shared, double-buffered via registers.
// ---------------------------------------------------------------------------
__global__ void __launch_bounds__(256, 2)
k_fuse(const float* __restrict__ x,
       const float* __restrict__ g2, const float* __restrict__ be2,
       const float* __restrict__ Wf1, const float* __restrict__ bf1,
       const float* __restrict__ gf1, const float* __restrict__ bef1,
       const float* __restrict__ Wf2, const float* __restrict__ bf2,
       const float* __restrict__ gf2, const float* __restrict__ bef2,
       const float* __restrict__ Wf3, const float* __restrict__ bf3,
       float* __restrict__ out)
{
    extern __shared__ float sm[];
    float* multiT = sm;                   // [192][34] = 6528 ; h2T aliases [128][34]
    float* h2T    = sm;
    float* h1T    = sm + 6528;            // [256][34] = 8704
    float* ws     = sm + 15232;           // 2 x 4096 = 8192
    float* b1S    = sm + 23424;           // 256
    float* g1S    = b1S + 256;            // 256
    float* e1S    = g1S + 256;            // 256
    float* b2S    = sm + 24192;           // 128
    float* g2S    = b2S + 128;            // 128
    float* e2S    = g2S + 128;            // 128
    float* wf3S   = sm + 24576;           // 384
    float* fwS    = sm + 24960;           // 96
    float* bf3S   = sm + 25056;           // 4
    int*   idxS   = (int*)(sm + 25060);   // 256
    float* g2v    = sm + 25316;           // 64
    float* be2v   = g2v + 64;             // 64   -> total 25444 floats

    const int tid  = threadIdx.x;
    const int lane = tid & 31;
    const int wrp  = tid >> 5;
    const int p0   = blockIdx.x * PTB;
    const int base = 4 * wrp;             // warp's first point (4 pts/warp)

    // ---- stage small constants ----
    { b1S[tid]=bf1[tid]; g1S[tid]=gf1[tid]; e1S[tid]=bef1[tid]; }
    if (tid < 128) { b2S[tid]=bf2[tid]; g2S[tid]=gf2[tid]; e2S[tid]=bef2[tid]; }
    for (int i = tid; i < 384; i += 256) wf3S[i] = Wf3[i];   // FIXED: full 384-entry stage
    if (tid < 96)  fwS[tid]=g_fw[p0*3 + tid];
    if (tid < 3)   bf3S[tid]=bf3[tid];
    idxS[tid] = g_idx[p0*8 + tid];
    if (tid < 64) { g2v[tid]=g2[tid]; be2v[tid]=be2[tid]; }
    __syncthreads();

    // ---- gather + edge-conv epilogue + max + fw-weighting -> multiT ----
    {
        int pt = tid & 31, grp = tid >> 5, d0 = grp * 8;
        int p = p0 + pt;
        int bbase = p & ~(NN - 1);
        float4 a0 = *(const float4*)(g_A + p*64 + d0);
        float4 a1 = *(const float4*)(g_A + p*64 + d0 + 4);
        float4 gg0 = *(const float4*)(g2v + d0);
        float4 gg1 = *(const float4*)(g2v + d0 + 4);
        float4 ee0 = *(const float4*)(be2v + d0);
        float4 ee1 = *(const float4*)(be2v + d0 + 4);
        float m[8];
        #pragma unroll
        for (int u = 0; u < 8; u++) m[u] = -3.4e38f;
        #pragma unroll
        for (int k = 0; k < 8; k++) {
            int j = idxS[pt*8 + k];
            const float4* bp = (const float4*)(g_Bf + (bbase + j)*64 + d0);
            float4 v0 = bp[0], v1 = bp[1];
            m[0] = fmaxf(m[0], leaky(fmaf(a0.x + v0.x, gg0.x, ee0.x)));
            m[1] = fmaxf(m[1], leaky(fmaf(a0.y + v0.y, gg0.y, ee0.y)));
            m[2] = fmaxf(m[2], leaky(fmaf(a0.z + v0.z, gg0.z, ee0.z)));
            m[3] = fmaxf(m[3], leaky(fmaf(a0.w + v0.w, gg0.w, ee0.w)));
            m[4] = fmaxf(m[4], leaky(fmaf(a1.x + v1.x, gg1.x, ee1.x)));
            m[5] = fmaxf(m[5], leaky(fmaf(a1.y + v1.y, gg1.y, ee1.y)));
            m[6] = fmaxf(m[6], leaky(fmaf(a1.z + v1.z, gg1.z, ee1.z)));
            m[7] = fmaxf(m[7], leaky(fmaf(a1.w + v1.w, gg1.w, ee1.w)));
        }
        float fw0 = fwS[pt*3], fw1 = fwS[pt*3+1], fw2 = fwS[pt*3+2];
        #pragma unroll
        for (int dd = 0; dd < 8; dd++) {
            multiT[(d0+dd)*34 + pt]        = m[dd] * fw0;
            multiT[(64+d0+dd)*34 + pt]     = m[dd] * fw1;
            multiT[(128+d0+dd)*34 + pt]    = m[dd] * fw2;
        }
    }
    __syncthreads();

    // ---- layer 1: 192 -> 256 (12 chunks of K=16) ----
    unsigned long long acc[8][2];
    #pragma unroll
    for (int r = 0; r < 8; r++) { acc[r][0] = 0ull; acc[r][1] = 0ull; }

    // stage chunk 0
    #pragma unroll
    for (int u = 0; u < 4; u++) {
        *(float4*)(ws + (tid + u*256)*4) = *(const float4*)(Wf1 + (tid + u*256)*4);
    }
    __syncthreads();

    for (int c = 0; c < 12; c++) {
        float4 pf[4];
        if (c < 11) {
            #pragma unroll
            for (int u = 0; u < 4; u++)
                pf[u] = *(const float4*)(Wf1 + (c+1)*4096 + (tid + u*256)*4);
        }
        const float* wb = ws + (c & 1) * 4096;
        #pragma unroll
        for (int kk = 0; kk < 16; kk++) {
            const float* mrow = multiT + (c*16 + kk)*34 + base;
            unsigned long long in0 = *(const unsigned long long*)(mrow);
            unsigned long long in1 = *(const unsigned long long*)(mrow + 2);
            #pragma unroll
            for (int r = 0; r < 8; r++) {
                unsigned long long wp = pack2(wb[kk*256 + lane + 32*r]);
                acc[r][0] = ffma2(in0, wp, acc[r][0]);
                acc[r][1] = ffma2(in1, wp, acc[r][1]);
            }
        }
        if (c < 11) {
            float* wd = ws + ((c+1) & 1) * 4096;
            #pragma unroll
            for (int u = 0; u < 4; u++)
                *(float4*)(wd + (tid + u*256)*4) = pf[u];
        }
        __syncthreads();
    }
    // epilogue -> h1T [o][pt]
    #pragma unroll
    for (int r = 0; r < 8; r++) {
        int o = lane + 32*r;
        float bb = b1S[o], gg = g1S[o], ee = e1S[o];
        #pragma unroll
        for (int q = 0; q < 2; q++) {
            float2 v = *(float2*)&acc[r][q];
            float2 hv;
            hv.x = leaky(fmaf(v.x + bb, gg, ee));
            hv.y = leaky(fmaf(v.y + bb, gg, ee));
            *(float2*)(h1T + o*34 + base + 2*q) = hv;
        }
    }
    __syncthreads();

    // ---- layer 2: 256 -> 128 (16 chunks of K=16) ----
    unsigned long long a2[4][2];
    #pragma unroll
    for (int r = 0; r < 4; r++) { a2[r][0] = 0ull; a2[r][1] = 0ull; }

    #pragma unroll
    for (int u = 0; u < 2; u++) {
        *(float4*)(ws + (tid + u*256)*4) = *(const float4*)(Wf2 + (tid + u*256)*4);
    }
    __syncthreads();

    for (int c = 0; c < 16; c++) {
        float4 pf[2];
        if (c < 15) {
            #pragma unroll
            for (int u = 0; u < 2; u++)
                pf[u] = *(const float4*)(Wf2 + (c+1)*2048 + (tid + u*256)*4);
        }
        const float* wb = ws + (c & 1) * 2048;
        #pragma unroll
        for (int kk = 0; kk < 16; kk++) {
            const float* hrow = h1T + (c*16 + kk)*34 + base;
            unsigned long long in0 = *(const unsigned long long*)(hrow);
            unsigned long long in1 = *(const unsigned long long*)(hrow + 2);
            #pragma unroll
            for (int r = 0; r < 4; r++) {
                unsigned long long wp = pack2(wb[kk*128 + lane + 32*r]);
                a2[r][0] = ffma2(in0, wp, a2[r][0]);
                a2[r][1] = ffma2(in1, wp, a2[r][1]);
            }
        }
        if (c < 15) {
            float* wd = ws + ((c+1) & 1) * 2048;
            #pragma unroll
            for (int u = 0; u < 2; u++)
                *(float4*)(wd + (tid + u*256)*4) = pf[u];
        }
        __syncthreads();
    }
    // epilogue -> h2T [o][pt]  (aliases dead multiT)
    #pragma unroll
    for (int r = 0; r < 4; r++) {
        int o = lane + 32*r;
        float bb = b2S[o], gg = g2S[o], ee = e2S[o];
        #pragma unroll
        for (int q = 0; q < 2; q++) {
            float2 v = *(float2*)&a2[r][q];
            float2 hv;
            hv.x = leaky(fmaf(v.x + bb, gg, ee));
            hv.y = leaky(fmaf(v.y + bb, gg, ee));
            *(float2*)(h2T + o*34 + base + 2*q) = hv;
        }
    }
    __syncthreads();

    // ---- layer 3: 128 -> 3 + residual ----
    if (tid < 96) {
        int pt = tid / 3, cc = tid - pt*3;
        float s0 = 0.f, s1 = 0.f;
        #pragma unroll 8
        for (int k = 0; k < 128; k += 2) {
            s0 = fmaf(h2T[k*34 + pt],     wf3S[k*3 + cc],     s0);
            s1 = fmaf(h2T[(k+1)*34 + pt], wf3S[(k+1)*3 + cc], s1);
        }
        int gp = p0 + pt;
        out[gp*3 + cc] = fmaf(0.1f, (s0 + s1) + bf3S[cc], x[gp*3 + cc]);
    }
}

// ---------------------------------------------------------------------------
extern "C" void kernel_launch(void* const* d_in, const int* in_sizes, int n_in,
                              void* d_out, int out_size)
{
    const float* x    = (const float*)d_in[0];
    const float* W1   = (const float*)d_in[1];
    const float* b1   = (const float*)d_in[2];
    const float* g1   = (const float*)d_in[3];
    const float* be1  = (const float*)d_in[4];
    const float* W2   = (const float*)d_in[5];
    const float* b2   = (const float*)d_in[6];
    const float* g2   = (const float*)d_in[7];
    const float* be2  = (const float*)d_in[8];
    const float* Ws1  = (const float*)d_in[9];
    const float* bs1  = (const float*)d_in[10];
    const float* Ws2  = (const float*)d_in[11];
    const float* bs2  = (const float*)d_in[12];
    const float* Wf1  = (const float*)d_in[13];
    const float* bf1  = (const float*)d_in[14];
    const float* gf1  = (const float*)d_in[15];
    const float* bef1 = (const float*)d_in[16];
    const float* Wf2  = (const float*)d_in[17];
    const float* bf2  = (const float*)d_in[18];
    const float* gf2  = (const float*)d_in[19];
    const float* bef2 = (const float*)d_in[20];
    const float* Wf3  = (const float*)d_in[21];
    const float* bf3  = (const float*)d_in[22];
    float* out = (float*)d_out;

    const int SM1 = 17540 * 4;   // k_prep shared bytes
    const int SM2 = 49664;       // k_knn shared bytes
    const int SM4 = 25444 * 4;   // k_fuse shared bytes (~101.8KB)

    cudaFuncSetAttribute(k_prep, cudaFuncAttributeMaxDynamicSharedMemorySize, SM1);
    cudaFuncSetAttribute(k_knn,  cudaFuncAttributeMaxDynamicSharedMemorySize, SM2);
    cudaFuncSetAttribute(k_fuse, cudaFuncAttributeMaxDynamicSharedMemorySize, SM4);

    k_prep<<<256, 256, SM1>>>(x, W1, b1, g1, be1, W2, b2, Ws1, bs1, Ws2, bs2);
    k_knn<<<dim3(32, 8), 256, SM2>>>(x);
    k_fuse<<<PTS/PTB, 256, SM4>>>(x, g2, be2, Wf1, bf1, gf1, bef1,
                                  Wf2, bf2, gf2, bef2, Wf3, bf3, out);
}

// round 4
// speedup vs baseline: 1.2915x; 1.0316x over previous
#include <cuda_runtime.h>
#include <math.h>

// Problem constants
#define BB 8
#define NN 2048
#define PTS (BB*NN)      // 16384
#define DD 64
#define KK 8
#define LV 3
#define H1 256
#define H2 128
#define PTB 32           // points per k_fuse block

// Scratch (device globals; no allocation allowed)
__device__ float g_A  [PTS*DD];
__device__ float g_Bf [PTS*DD];
__device__ float g_fw [PTS*LV];
__device__ int   g_idx[PTS*KK];

__device__ __forceinline__ float leaky(float v){ return v > 0.f ? v : 0.2f*v; }

__device__ __forceinline__ unsigned long long ffma2(unsigned long long a, unsigned long long b, unsigned long long c){
    unsigned long long d;
    asm("fma.rn.f32x2 %0, %1, %2, %3;" : "=l"(d) : "l"(a), "l"(b), "l"(c));
    return d;
}
__device__ __forceinline__ unsigned long long pack2(float w){
    unsigned long long r;
    asm("mov.b64 %0, {%1, %1};" : "=l"(r) : "f"(w));
    return r;
}

// ---------------------------------------------------------------------------
// K1: per-point prep: feat = leaky((x@W1+b1)*g1+be1);
//     A = feat@W2[:64] + b2 ; Bf = feat@W2[64:] ;
//     fw = sigmoid(relu(x@Ws1+bs1)@Ws2+bs2)
// ---------------------------------------------------------------------------
__global__ void k_prep(const float* __restrict__ x,
                       const float* __restrict__ W1, const float* __restrict__ b1,
                       const float* __restrict__ g1, const float* __restrict__ be1,
                       const float* __restrict__ W2, const float* __restrict__ b2,
                       const float* __restrict__ Ws1, const float* __restrict__ bs1,
                       const float* __restrict__ Ws2, const float* __restrict__ bs2)
{
    extern __shared__ float sm[];
    float* W2s   = sm;               // 128*64 = 8192
    float* featS = W2s + 8192;       // 64*65  = 4160 (padded)
    float* ssS   = featS + 4160;     // 64*64  = 4096
    float* W1s   = ssS + 4096;       // 192
    float* Ws1s  = W1s + 192;        // 192
    float* Ws2s  = Ws1s + 192;       // 192
    float* b1v   = Ws2s + 192;       // 64
    float* g1v   = b1v + 64;
    float* be1v  = g1v + 64;
    float* b2v   = be1v + 64;
    float* bs1v  = b2v + 64;
    float* bs2v  = bs1v + 64;        // 4
    float* xs    = bs2v + 4;         // 192

    const int tid = threadIdx.x;
    const int p0  = blockIdx.x * 64;

    for (int i = tid; i < 8192; i += 256) W2s[i] = W2[i];
    for (int i = tid; i < 192; i += 256) { W1s[i] = W1[i]; Ws1s[i] = Ws1[i]; Ws2s[i] = Ws2[i]; xs[i] = x[p0*3 + i]; }
    if (tid < 64) { b1v[tid]=b1[tid]; g1v[tid]=g1[tid]; be1v[tid]=be1[tid]; b2v[tid]=b2[tid]; bs1v[tid]=bs1[tid]; }
    if (tid < 3)  bs2v[tid] = bs2[tid];
    __syncthreads();

    for (int i = tid; i < 4096; i += 256) {
        int pt = i >> 6, d = i & 63;
        float x0 = xs[pt*3], x1 = xs[pt*3+1], x2 = xs[pt*3+2];
        float f = fmaf(x2, W1s[128+d], fmaf(x1, W1s[64+d], fmaf(x0, W1s[d], b1v[d])));
        f = fmaf(f, g1v[d], be1v[d]);
        featS[pt*65 + d] = leaky(f);
        float s = fmaf(x2, Ws1s[128+d], fmaf(x1, Ws1s[64+d], fmaf(x0, Ws1s[d], bs1v[d])));
        ssS[pt*64 + d] = s > 0.f ? s : 0.f;
    }
    __syncthreads();

    if (tid < 192) {
        int pt = tid / 3, l = tid - pt*3;
        float s = bs2v[l];
        #pragma unroll 8
        for (int d = 0; d < 64; d++) s = fmaf(ssS[pt*64 + d], Ws2s[d*3 + l], s);
        g_fw[(p0+pt)*3 + l] = 1.f / (1.f + expf(-s));
    }

    // A / Bf : thread = (pt, group of 16 output dims); FFMA2-paired outputs
    {
        int pt  = tid & 63;
        int grp = tid >> 6;
        unsigned long long accA[8], accB[8];
        #pragma unroll
        for (int u = 0; u < 8; u++) {
            accA[u] = *(const unsigned long long*)(b2v + grp*16 + 2*u);
            accB[u] = 0ull;
        }
        for (int d = 0; d < 64; d++) {
            unsigned long long fv2 = pack2(featS[pt*65 + d]);
            const unsigned long long* wa = (const unsigned long long*)(W2s + d*64       + grp*16);
            const unsigned long long* wb = (const unsigned long long*)(W2s + (64+d)*64  + grp*16);
            #pragma unroll
            for (int u = 0; u < 8; u++) {
                accA[u] = ffma2(wa[u], fv2, accA[u]);
                accB[u] = ffma2(wb[u], fv2, accB[u]);
            }
        }
        float2* pA = (float2*)(g_A  + (p0+pt)*64 + grp*16);
        float2* pB = (float2*)(g_Bf + (p0+pt)*64 + grp*16);
        #pragma unroll
        for (int u = 0; u < 8; u++) {
            pA[u] = *(float2*)&accA[u];
            pB[u] = *(float2*)&accB[u];
        }
    }
}

// ---------------------------------------------------------------------------
// K2: KNN. grid (32, 8): 64 points/block, 4 j-splits x 64 pts = 256 threads.
// ---------------------------------------------------------------------------
__global__ void k_knn(const float* __restrict__ x)
{
    extern __shared__ float sm[];
    float4* xsh = (float4*)sm;            // 2048 * 4 floats
    float*  md  = sm + 8192;              // 64*33
    int*    mi  = (int*)(md + 64*33);     // 64*33

    const int tid = threadIdx.x;
    const int b   = blockIdx.y;
    const int pl0 = blockIdx.x * 64;

    for (int j = tid; j < NN; j += 256) {
        const float* xp = x + (b*NN + j)*3;
        float x0 = xp[0], x1 = xp[1], x2 = xp[2];
        float n  = fmaf(x2, x2, fmaf(x1, x1, x0*x0));
        xsh[j] = make_float4(x0, x1, x2, n);
    }
    __syncthreads();

    const int pt = tid & 63, split = tid >> 6;
    float4 xi = xsh[pl0 + pt];
    float bd[8]; int bi[8];
    #pragma unroll
    for (int s = 0; s < 8; s++) { bd[s] = 3.4e38f; bi[s] = 0x7fffffff; }

    const int j0 = split * 512;
    #pragma unroll 4
    for (int j = j0; j < j0 + 512; j++) {
        float4 xj = xsh[j];
        float dot = fmaf(xi.z, xj.z, fmaf(xi.y, xj.y, xi.x*xj.x));
        float d2  = fmaf(-2.f, dot, xi.w + xj.w);
        if (d2 < bd[7]) {
            int pos = 7;
            #pragma unroll
            for (int s = 6; s >= 0; s--) if (d2 < bd[s]) pos = s;
            #pragma unroll
            for (int s = 7; s >= 1; s--) if (s > pos) { bd[s] = bd[s-1]; bi[s] = bi[s-1]; }
            bd[pos] = d2; bi[pos] = j;
        }
    }
    #pragma unroll
    for (int s = 0; s < 8; s++) { md[pt*33 + split*8 + s] = bd[s]; mi[pt*33 + split*8 + s] = bi[s]; }
    __syncthreads();

    if (tid < 64) {
        float fd[8]; int fi[8];
        #pragma unroll
        for (int s = 0; s < 8; s++) { fd[s] = 3.4e38f; fi[s] = 0x7fffffff; }
        for (int c = 0; c < 32; c++) {
            float cd = md[tid*33 + c]; int ci = mi[tid*33 + c];
            bool ins = (cd < fd[7]) || (cd == fd[7] && ci < fi[7]);
            if (ins) {
                int pos = 7;
                #pragma unroll
                for (int s = 6; s >= 0; s--) if (cd < fd[s] || (cd == fd[s] && ci < fi[s])) pos = s;
                #pragma unroll
                for (int s = 7; s >= 1; s--) if (s > pos) { fd[s] = fd[s-1]; fi[s] = fi[s-1]; }
                fd[pos] = cd; fi[pos] = ci;
            }
        }
        int gp = b*NN + pl0 + tid;
        #pragma unroll
        for (int s = 0; s < 8; s++) g_idx[gp*8 + s] = fi[s];
    }
}

// ---------------------------------------------------------------------------
// K3 (fused): gather+edge-max+fw -> multiT (smem), then fusion MLP.
// 32 points/block, 256 threads, ~101.8KB smem -> 2 blocks/SM.
// Warp tile L1: 128 outs x 8 pts ; L2: 64 outs x 8 pts.
// ---------------------------------------------------------------------------
__global__ void __launch_bounds__(256, 2)
k_fuse(const float* __restrict__ x,
       const float* __restrict__ g2, const float* __restrict__ be2,
       const float* __restrict__ Wf1, const float* __restrict__ bf1,
       const float* __restrict__ gf1, const float* __restrict__ bef1,
       const float* __restrict__ Wf2, const float* __restrict__ bf2,
       const float* __restrict__ gf2, const float* __restrict__ bef2,
       const float* __restrict__ Wf3, const float* __restrict__ bf3,
       float* __restrict__ out)
{
    extern __shared__ float sm[];
    float* multiT = sm;                   // [192][34] = 6528 ; h2T aliases [128][34]
    float* h2T    = sm;
    float* h1T    = sm + 6528;            // [256][34] = 8704
    float* ws     = sm + 15232;           // 2 x 4096 = 8192
    float* b1S    = sm + 23424;           // 256
    float* g1S    = b1S + 256;            // 256
    float* e1S    = g1S + 256;            // 256
    float* b2S    = sm + 24192;           // 128
    float* g2S    = b2S + 128;            // 128
    float* e2S    = g2S + 128;            // 128
    float* wf3S   = sm + 24576;           // 384
    float* fwS    = sm + 24960;           // 96
    float* bf3S   = sm + 25056;           // 4
    int*   idxS   = (int*)(sm + 25060);   // 256
    float* g2v    = sm + 25316;           // 64
    float* be2v   = g2v + 64;             // 64   -> total 25444 floats

    const int tid  = threadIdx.x;
    const int lane = tid & 31;
    const int wrp  = tid >> 5;
    const int p0   = blockIdx.x * PTB;
    const int pg   = wrp & 3;             // point group: 8 pts
    const int oh   = wrp >> 2;            // output half
    const int pbase = pg * 8;

    // ---- stage small constants ----
    { b1S[tid]=bf1[tid]; g1S[tid]=gf1[tid]; e1S[tid]=bef1[tid]; }
    if (tid < 128) { b2S[tid]=bf2[tid]; g2S[tid]=gf2[tid]; e2S[tid]=bef2[tid]; }
    for (int i = tid; i < 384; i += 256) wf3S[i] = Wf3[i];
    if (tid < 96)  fwS[tid]=g_fw[p0*3 + tid];
    if (tid < 3)   bf3S[tid]=bf3[tid];
    idxS[tid] = g_idx[p0*8 + tid];
    if (tid < 64) { g2v[tid]=g2[tid]; be2v[tid]=be2[tid]; }
    __syncthreads();

    // ---- gather + edge-conv epilogue + max + fw-weighting -> multiT ----
    {
        int pt = tid & 31, grp = tid >> 5, d0 = grp * 8;
        int p = p0 + pt;
        int bbase = p & ~(NN - 1);
        float4 a0 = *(const float4*)(g_A + p*64 + d0);
        float4 a1 = *(const float4*)(g_A + p*64 + d0 + 4);
        float4 gg0 = *(const float4*)(g2v + d0);
        float4 gg1 = *(const float4*)(g2v + d0 + 4);
        float4 ee0 = *(const float4*)(be2v + d0);
        float4 ee1 = *(const float4*)(be2v + d0 + 4);
        float m[8];
        #pragma unroll
        for (int u = 0; u < 8; u++) m[u] = -3.4e38f;
        #pragma unroll
        for (int k = 0; k < 8; k++) {
            int j = idxS[pt*8 + k];
            const float4* bp = (const float4*)(g_Bf + (bbase + j)*64 + d0);
            float4 v0 = bp[0], v1 = bp[1];
            m[0] = fmaxf(m[0], leaky(fmaf(a0.x + v0.x, gg0.x, ee0.x)));
            m[1] = fmaxf(m[1], leaky(fmaf(a0.y + v0.y, gg0.y, ee0.y)));
            m[2] = fmaxf(m[2], leaky(fmaf(a0.z + v0.z, gg0.z, ee0.z)));
            m[3] = fmaxf(m[3], leaky(fmaf(a0.w + v0.w, gg0.w, ee0.w)));
            m[4] = fmaxf(m[4], leaky(fmaf(a1.x + v1.x, gg1.x, ee1.x)));
            m[5] = fmaxf(m[5], leaky(fmaf(a1.y + v1.y, gg1.y, ee1.y)));
            m[6] = fmaxf(m[6], leaky(fmaf(a1.z + v1.z, gg1.z, ee1.z)));
            m[7] = fmaxf(m[7], leaky(fmaf(a1.w + v1.w, gg1.w, ee1.w)));
        }
        float fw0 = fwS[pt*3], fw1 = fwS[pt*3+1], fw2 = fwS[pt*3+2];
        #pragma unroll
        for (int dd = 0; dd < 8; dd++) {
            multiT[(d0+dd)*34 + pt]        = m[dd] * fw0;
            multiT[(64+d0+dd)*34 + pt]     = m[dd] * fw1;
            multiT[(128+d0+dd)*34 + pt]    = m[dd] * fw2;
        }
    }
    __syncthreads();

    // ---- layer 1: 192 -> 256 (12 chunks of K=16) ----
    // warp tile: outs oh*128 + 32*i + lane (i<4)  x  pts pbase..pbase+7 (q<4 pairs)
    unsigned long long acc[4][4];
    #pragma unroll
    for (int i = 0; i < 4; i++)
        #pragma unroll
        for (int q = 0; q < 4; q++) acc[i][q] = 0ull;

    // stage chunk 0
    #pragma unroll
    for (int u = 0; u < 4; u++) {
        *(float4*)(ws + (tid + u*256)*4) = *(const float4*)(Wf1 + (tid + u*256)*4);
    }
    __syncthreads();

    for (int c = 0; c < 12; c++) {
        float4 pf[4];
        if (c < 11) {
            #pragma unroll
            for (int u = 0; u < 4; u++)
                pf[u] = *(const float4*)(Wf1 + (c+1)*4096 + (tid + u*256)*4);
        }
        const float* wb = ws + (c & 1) * 4096;
        #pragma unroll
        for (int kk = 0; kk < 16; kk++) {
            const unsigned long long* mrow =
                (const unsigned long long*)(multiT + (c*16 + kk)*34 + pbase);
            unsigned long long in0 = mrow[0], in1 = mrow[1], in2 = mrow[2], in3 = mrow[3];
            const float* wrow = wb + kk*256 + oh*128 + lane;
            #pragma unroll
            for (int i = 0; i < 4; i++) {
                unsigned long long wp = pack2(wrow[32*i]);
                acc[i][0] = ffma2(in0, wp, acc[i][0]);
                acc[i][1] = ffma2(in1, wp, acc[i][1]);
                acc[i][2] = ffma2(in2, wp, acc[i][2]);
                acc[i][3] = ffma2(in3, wp, acc[i][3]);
            }
        }
        if (c < 11) {
            float* wd = ws + ((c+1) & 1) * 4096;
            #pragma unroll
            for (int u = 0; u < 4; u++)
                *(float4*)(wd + (tid + u*256)*4) = pf[u];
        }
        __syncthreads();
    }
    // epilogue -> h1T [o][pt]
    #pragma unroll
    for (int i = 0; i < 4; i++) {
        int o = oh*128 + 32*i + lane;
        float bb = b1S[o], gg = g1S[o], ee = e1S[o];
        #pragma unroll
        for (int q = 0; q < 4; q++) {
            float2 v = *(float2*)&acc[i][q];
            float2 hv;
            hv.x = leaky(fmaf(v.x + bb, gg, ee));
            hv.y = leaky(fmaf(v.y + bb, gg, ee));
            *(float2*)(h1T + o*34 + pbase + 2*q) = hv;
        }
    }
    __syncthreads();

    // ---- layer 2: 256 -> 128 (16 chunks of K=16) ----
    // warp tile: outs oh*64 + 32*i + lane (i<2)  x  pts pbase.. (q<4)
    unsigned long long a2[2][4];
    #pragma unroll
    for (int i = 0; i < 2; i++)
        #pragma unroll
        for (int q = 0; q < 4; q++) a2[i][q] = 0ull;

    #pragma unroll
    for (int u = 0; u < 2; u++) {
        *(float4*)(ws + (tid + u*256)*4) = *(const float4*)(Wf2 + (tid + u*256)*4);
    }
    __syncthreads();

    for (int c = 0; c < 16; c++) {
        float4 pf[2];
        if (c < 15) {
            #pragma unroll
            for (int u = 0; u < 2; u++)
                pf[u] = *(const float4*)(Wf2 + (c+1)*2048 + (tid + u*256)*4);
        }
        const float* wb = ws + (c & 1) * 2048;
        #pragma unroll
        for (int kk = 0; kk < 16; kk++) {
            const unsigned long long* hrow =
                (const unsigned long long*)(h1T + (c*16 + kk)*34 + pbase);
            unsigned long long in0 = hrow[0], in1 = hrow[1], in2 = hrow[2], in3 = hrow[3];
            const float* wrow = wb + kk*128 + oh*64 + lane;
            #pragma unroll
            for (int i = 0; i < 2; i++) {
                unsigned long long wp = pack2(wrow[32*i]);
                a2[i][0] = ffma2(in0, wp, a2[i][0]);
                a2[i][1] = ffma2(in1, wp, a2[i][1]);
                a2[i][2] = ffma2(in2, wp, a2[i][2]);
                a2[i][3] = ffma2(in3, wp, a2[i][3]);
            }
        }
        if (c < 15) {
            float* wd = ws + ((c+1) & 1) * 2048;
            #pragma unroll
            for (int u = 0; u < 2; u++)
                *(float4*)(wd + (tid + u*256)*4) = pf[u];
        }
        __syncthreads();
    }
    // epilogue -> h2T [o][pt]  (aliases dead multiT)
    #pragma unroll
    for (int i = 0; i < 2; i++) {
        int o = oh*64 + 32*i + lane;
        float bb = b2S[o], gg = g2S[o], ee = e2S[o];
        #pragma unroll
        for (int q = 0; q < 4; q++) {
            float2 v = *(float2*)&a2[i][q];
            float2 hv;
            hv.x = leaky(fmaf(v.x + bb, gg, ee));
            hv.y = leaky(fmaf(v.y + bb, gg, ee));
            *(float2*)(h2T + o*34 + pbase + 2*q) = hv;
        }
    }
    __syncthreads();

    // ---- layer 3: 128 -> 3 + residual ----
    if (tid < 96) {
        int pt = tid / 3, cc = tid - pt*3;
        float s0 = 0.f, s1 = 0.f;
        #pragma unroll 8
        for (int k = 0; k < 128; k += 2) {
            s0 = fmaf(h2T[k*34 + pt],     wf3S[k*3 + cc],     s0);
            s1 = fmaf(h2T[(k+1)*34 + pt], wf3S[(k+1)*3 + cc], s1);
        }
        int gp = p0 + pt;
        out[gp*3 + cc] = fmaf(0.1f, (s0 + s1) + bf3S[cc], x[gp*3 + cc]);
    }
}

// ---------------------------------------------------------------------------
extern "C" void kernel_launch(void* const* d_in, const int* in_sizes, int n_in,
                              void* d_out, int out_size)
{
    const float* x    = (const float*)d_in[0];
    const float* W1   = (const float*)d_in[1];
    const float* b1   = (const float*)d_in[2];
    const float* g1   = (const float*)d_in[3];
    const float* be1  = (const float*)d_in[4];
    const float* W2   = (const float*)d_in[5];
    const float* b2   = (const float*)d_in[6];
    const float* g2   = (const float*)d_in[7];
    const float* be2  = (const float*)d_in[8];
    const float* Ws1  = (const float*)d_in[9];
    const float* bs1  = (const float*)d_in[10];
    const float* Ws2  = (const float*)d_in[11];
    const float* bs2  = (const float*)d_in[12];
    const float* Wf1  = (const float*)d_in[13];
    const float* bf1  = (const float*)d_in[14];
    const float* gf1  = (const float*)d_in[15];
    const float* bef1 = (const float*)d_in[16];
    const float* Wf2  = (const float*)d_in[17];
    const float* bf2  = (const float*)d_in[18];
    const float* gf2  = (const float*)d_in[19];
    const float* bef2 = (const float*)d_in[20];
    const float* Wf3  = (const float*)d_in[21];
    const float* bf3  = (const float*)d_in[22];
    float* out = (float*)d_out;

    const int SM1 = 17540 * 4;   // k_prep shared bytes
    const int SM2 = 49664;       // k_knn shared bytes
    const int SM4 = 25444 * 4;   // k_fuse shared bytes (~101.8KB)

    cudaFuncSetAttribute(k_prep, cudaFuncAttributeMaxDynamicSharedMemorySize, SM1);
    cudaFuncSetAttribute(k_knn,  cudaFuncAttributeMaxDynamicSharedMemorySize, SM2);
    cudaFuncSetAttribute(k_fuse, cudaFuncAttributeMaxDynamicSharedMemorySize, SM4);

    k_prep<<<256, 256, SM1>>>(x, W1, b1, g1, be1, W2, b2, Ws1, bs1, Ws2, bs2);
    k_knn<<<dim3(32, 8), 256, SM2>>>(x);
    k_fuse<<<PTS/PTB, 256, SM4>>>(x, g2, be2, Wf1, bf1, gf1, bef1,
                                  Wf2, bf2, gf2, bef2, Wf3, bf3, out);
}